// round 1
// baseline (speedup 1.0000x reference)
#include <cuda_runtime.h>

#define T_STEPS 1000
#define BATCH   512
#define INP     26
#define H1      64
#define H2      32
#define MB      4
#define NBLK    (BATCH / MB)
#define XPAD    28

typedef unsigned long long ull;

// Scratch: x transposed to [t][b][i] for coalesced per-step reads.
__device__ float g_xT[T_STEPS * BATCH * INP];

// ---------- f32x2 helpers ----------
__device__ __forceinline__ ull pack2(float lo, float hi) {
    ull r;
    asm("mov.b64 %0, {%1, %2};" : "=l"(r) : "f"(lo), "f"(hi));
    return r;
}
__device__ __forceinline__ void ffma2(ull& d, ull a, ull b) {
    asm("fma.rn.f32x2 %0, %1, %2, %0;" : "+l"(d) : "l"(a), "l"(b));
}
__device__ __forceinline__ float hsum2(ull v) {
    float lo, hi;
    asm("mov.b64 {%0, %1}, %2;" : "=f"(lo), "=f"(hi) : "l"(v));
    return lo + hi;
}
// ---------- fast activations (accurate: ~1e-7 rel err) ----------
__device__ __forceinline__ float ex2f(float x) { float y; asm("ex2.approx.f32 %0, %1;" : "=f"(y) : "f"(x)); return y; }
__device__ __forceinline__ float rcpf(float x) { float y; asm("rcp.approx.f32 %0, %1;" : "=f"(y) : "f"(x)); return y; }
__device__ __forceinline__ float sigm(float x) { return rcpf(1.0f + ex2f(-1.4426950408889634f * x)); }
__device__ __forceinline__ float tanhx(float x) {
    float t = ex2f(2.8853900817779268f * x);   // e^(2x)
    return 1.0f - 2.0f * rcpf(t + 1.0f);
}

// ---------- transpose x: [B,26,T] -> [T, B*26] ----------
__global__ void xpose_kernel(const float* __restrict__ x) {
    __shared__ float tile[32][33];
    int t0 = blockIdx.x * 32;
    int r0 = blockIdx.y * 32;   // r = b*26 + i, total 13312 rows (multiple of 32)
    int tx = threadIdx.x, ty = threadIdx.y;
#pragma unroll
    for (int k = 0; k < 4; k++) {
        int t = t0 + tx;
        int r = r0 + ty + k * 8;
        if (t < T_STEPS) tile[ty + k * 8][tx] = x[r * T_STEPS + t];
    }
    __syncthreads();
#pragma unroll
    for (int k = 0; k < 4; k++) {
        int t = t0 + ty + k * 8;
        int r = r0 + tx;
        if (t < T_STEPS) g_xT[t * (BATCH * INP) + r] = tile[tx][ty + k * 8];
    }
}

// ---------- persistent 2-layer LSTM scan + FC head ----------
__global__ __launch_bounds__(256, 1)
void lstm_kernel(const float* __restrict__ w_ih1, const float* __restrict__ w_hh1,
                 const float* __restrict__ b_ih1, const float* __restrict__ b_hh1,
                 const float* __restrict__ w_ih2, const float* __restrict__ w_hh2,
                 const float* __restrict__ b_ih2, const float* __restrict__ b_hh2,
                 const float* __restrict__ w_fc1, const float* __restrict__ b_fc1,
                 const float* __restrict__ w_fc2, const float* __restrict__ b_fc2,
                 float* __restrict__ out) {
    __shared__ __align__(16) float h1s[MB][H1];
    __shared__ __align__(16) float h2s[MB][H2];
    __shared__ __align__(16) float xs[2][MB][XPAD];
    __shared__ float g1s[4 * H1][5];   // padded stride 5 -> conflict-free
    __shared__ float g2s[4 * H2][5];
    __shared__ float fcs[MB][16];

    const int tid = threadIdx.x;
    const int b0  = blockIdx.x * MB;

    // ---- load weights into registers, packed along K ----
    ull wi1[13], wh1[32];
    {
        const float* wr = w_ih1 + tid * INP;
#pragma unroll
        for (int j = 0; j < 13; j++) wi1[j] = pack2(wr[2 * j], wr[2 * j + 1]);
        wr = w_hh1 + tid * H1;
#pragma unroll
        for (int j = 0; j < 32; j++) wh1[j] = pack2(wr[2 * j], wr[2 * j + 1]);
    }
    const float bias1 = b_ih1[tid] + b_hh1[tid];

    ull wi2[32], wh2[16];
    float bias2 = 0.0f;
    if (tid < 4 * H2) {
        const float* wr = w_ih2 + tid * H1;
#pragma unroll
        for (int j = 0; j < 32; j++) wi2[j] = pack2(wr[2 * j], wr[2 * j + 1]);
        wr = w_hh2 + tid * H2;
#pragma unroll
        for (int j = 0; j < 16; j++) wh2[j] = pack2(wr[2 * j], wr[2 * j + 1]);
        bias2 = b_ih2[tid] + b_hh2[tid];
    }

    float c1[MB], c2[MB];
#pragma unroll
    for (int r = 0; r < MB; r++) { c1[r] = 0.0f; c2[r] = 0.0f; }

    // ---- init shared state + first x tile ----
    for (int idx = tid; idx < MB * H1; idx += 256) ((float*)h1s)[idx] = 0.0f;
    for (int idx = tid; idx < MB * H2; idx += 256) ((float*)h2s)[idx] = 0.0f;
    if (tid < MB * INP) {
        int r = tid / INP, i = tid % INP;
        xs[0][r][i] = g_xT[b0 * INP + tid];
    }
    __syncthreads();

    const int r_p = tid / INP, i_p = tid % INP;

    for (int t = 0; t < T_STEPS; t++) {
        const int buf = t & 1, nbuf = buf ^ 1;

        // prefetch x[t+1] (contiguous 104 floats per block)
        float xpre = 0.0f;
        const bool dopre = (tid < MB * INP) && (t + 1 < T_STEPS);
        if (dopre) xpre = g_xT[(t + 1) * (BATCH * INP) + b0 * INP + tid];

        // ===== layer-1 gates: every thread owns one of the 256 gate rows =====
        ull acc[MB];
#pragma unroll
        for (int r = 0; r < MB; r++) acc[r] = pack2(bias1, 0.0f);

#pragma unroll
        for (int j = 0; j < 16; j++) {
#pragma unroll
            for (int r = 0; r < MB; r++) {
                ulonglong2 p = *(const ulonglong2*)&h1s[r][4 * j];
                ffma2(acc[r], wh1[2 * j],     p.x);
                ffma2(acc[r], wh1[2 * j + 1], p.y);
            }
        }
#pragma unroll
        for (int j = 0; j < 6; j++) {
#pragma unroll
            for (int r = 0; r < MB; r++) {
                ulonglong2 p = *(const ulonglong2*)&xs[buf][r][4 * j];
                ffma2(acc[r], wi1[2 * j],     p.x);
                ffma2(acc[r], wi1[2 * j + 1], p.y);
            }
        }
#pragma unroll
        for (int r = 0; r < MB; r++) {
            ull v = *(const ull*)&xs[buf][r][24];
            ffma2(acc[r], wi1[12], v);
        }
        const bool is_tanh1 = (tid >= 128) && (tid < 192);
#pragma unroll
        for (int r = 0; r < MB; r++) {
            float v = hsum2(acc[r]);
            g1s[tid][r] = is_tanh1 ? tanhx(v) : sigm(v);
        }
        __syncthreads();   // B1

        if (dopre) xs[nbuf][r_p][i_p] = xpre;

        // ===== layer-1 cell update: threads 0..63 =====
        if (tid < H1) {
#pragma unroll
            for (int r = 0; r < MB; r++) {
                float iv = g1s[tid][r];
                float fv = g1s[H1 + tid][r];
                float gv = g1s[2 * H1 + tid][r];
                float ov = g1s[3 * H1 + tid][r];
                float c  = fv * c1[r] + iv * gv;
                c1[r] = c;
                h1s[r][tid] = ov * tanhx(c);
            }
        }
        __syncthreads();   // B2

        // ===== layer-2 gates: threads 0..127 =====
        if (tid < 4 * H2) {
            ull acc2[MB];
#pragma unroll
            for (int r = 0; r < MB; r++) acc2[r] = pack2(bias2, 0.0f);
#pragma unroll
            for (int j = 0; j < 16; j++) {
#pragma unroll
                for (int r = 0; r < MB; r++) {
                    ulonglong2 p = *(const ulonglong2*)&h1s[r][4 * j];
                    ffma2(acc2[r], wi2[2 * j],     p.x);
                    ffma2(acc2[r], wi2[2 * j + 1], p.y);
                }
            }
#pragma unroll
            for (int j = 0; j < 8; j++) {
#pragma unroll
                for (int r = 0; r < MB; r++) {
                    ulonglong2 p = *(const ulonglong2*)&h2s[r][4 * j];
                    ffma2(acc2[r], wh2[2 * j],     p.x);
                    ffma2(acc2[r], wh2[2 * j + 1], p.y);
                }
            }
            const bool is_tanh2 = (tid >= 64) && (tid < 96);
#pragma unroll
            for (int r = 0; r < MB; r++) {
                float v = hsum2(acc2[r]);
                g2s[tid][r] = is_tanh2 ? tanhx(v) : sigm(v);
            }
        }
        __syncthreads();   // B3

        // ===== layer-2 cell update: threads 0..31 =====
        // (no trailing barrier needed: next iter's B1+B2 order h2s/g2s hazards)
        if (tid < H2) {
#pragma unroll
            for (int r = 0; r < MB; r++) {
                float iv = g2s[tid][r];
                float fv = g2s[H2 + tid][r];
                float gv = g2s[2 * H2 + tid][r];
                float ov = g2s[3 * H2 + tid][r];
                float c  = fv * c2[r] + iv * gv;
                c2[r] = c;
                h2s[r][tid] = ov * tanhx(c);
            }
        }
    }
    __syncthreads();

    // ===== FC head on final h2 =====
    if (tid < MB * 16) {
        int r = tid >> 4, j = tid & 15;
        float a = b_fc1[j];
#pragma unroll
        for (int k = 0; k < H2; k++) a += w_fc1[j * H2 + k] * h2s[r][k];
        fcs[r][j] = fmaxf(a, 0.0f);
    }
    __syncthreads();
    if (tid < MB * 10) {
        int r = tid / 10, o = tid % 10;
        float a = b_fc2[o];
#pragma unroll
        for (int k = 0; k < 16; k++) a += w_fc2[o * 16 + k] * fcs[r][k];
        out[(b0 + r) * 10 + o] = a;
    }
}

extern "C" void kernel_launch(void* const* d_in, const int* in_sizes, int n_in,
                              void* d_out, int out_size) {
    const float* x     = (const float*)d_in[0];
    const float* w_ih1 = (const float*)d_in[1];
    const float* w_hh1 = (const float*)d_in[2];
    const float* b_ih1 = (const float*)d_in[3];
    const float* b_hh1 = (const float*)d_in[4];
    const float* w_ih2 = (const float*)d_in[5];
    const float* w_hh2 = (const float*)d_in[6];
    const float* b_ih2 = (const float*)d_in[7];
    const float* b_hh2 = (const float*)d_in[8];
    const float* w_fc1 = (const float*)d_in[9];
    const float* b_fc1 = (const float*)d_in[10];
    const float* w_fc2 = (const float*)d_in[11];
    const float* b_fc2 = (const float*)d_in[12];
    float* out = (float*)d_out;

    dim3 tb(32, 8);
    dim3 tg((T_STEPS + 31) / 32, (BATCH * INP) / 32);
    xpose_kernel<<<tg, tb>>>(x);

    lstm_kernel<<<NBLK, 256>>>(w_ih1, w_hh1, b_ih1, b_hh1,
                               w_ih2, w_hh2, b_ih2, b_hh2,
                               w_fc1, b_fc1, w_fc2, b_fc2, out);
}

// round 2
// speedup vs baseline: 1.0386x; 1.0386x over previous
#include <cuda_runtime.h>

#define T_STEPS 1000
#define BATCH   512
#define INP     26
#define H1      64
#define H2      32
#define MB      4
#define NBLK    (BATCH / MB)
#define SSTR    164          // floats per batch-row in step buffer (16B-mult, %32!=0)
#define NTHR    512

typedef unsigned long long ull;

// Scratch: x transposed to [t][b][i] for coalesced per-step reads.
__device__ float g_xT[T_STEPS * BATCH * INP];

// ---------- f32x2 helpers ----------
__device__ __forceinline__ ull pack2(float lo, float hi) {
    ull r; asm("mov.b64 %0, {%1, %2};" : "=l"(r) : "f"(lo), "f"(hi)); return r;
}
__device__ __forceinline__ void ffma2(ull& d, ull a, ull b) {
    asm("fma.rn.f32x2 %0, %1, %2, %0;" : "+l"(d) : "l"(a), "l"(b));
}
__device__ __forceinline__ float hsum2(ull v) {
    float lo, hi; asm("mov.b64 {%0, %1}, %2;" : "=f"(lo), "=f"(hi) : "l"(v)); return lo + hi;
}
__device__ __forceinline__ float ex2f(float x) { float y; asm("ex2.approx.f32 %0, %1;" : "=f"(y) : "f"(x)); return y; }
__device__ __forceinline__ float rcpf(float x) { float y; asm("rcp.approx.f32 %0, %1;" : "=f"(y) : "f"(x)); return y; }
// tanh(c) = 2*sigmoid(2c)-1
__device__ __forceinline__ float tanhc(float c) {
    return fmaf(2.0f, rcpf(1.0f + ex2f(-2.885390081777927f * c)), -1.0f);
}

// ---------- transpose x: [B,26,T] -> [T, B*26] ----------
__global__ void xpose_kernel(const float* __restrict__ x) {
    __shared__ float tile[32][33];
    int t0 = blockIdx.x * 32;
    int r0 = blockIdx.y * 32;
    int tx = threadIdx.x, ty = threadIdx.y;
#pragma unroll
    for (int k = 0; k < 4; k++) {
        int t = t0 + tx;
        int r = r0 + ty + k * 8;
        if (t < T_STEPS) tile[ty + k * 8][tx] = x[r * T_STEPS + t];
    }
    __syncthreads();
#pragma unroll
    for (int k = 0; k < 4; k++) {
        int t = t0 + ty + k * 8;
        int r = r0 + tx;
        if (t < T_STEPS) g_xT[t * (BATCH * INP) + r] = tile[tx][ty + k * 8];
    }
}

// Buffer row layout (floats): [0..31] x (26 real + 6 zero pad)
//                             [32..95] h1
//                             [96..127] h2copy (h2[t-1], staged)
//                             [128..159] h2new (h2[t])
__global__ __launch_bounds__(NTHR, 1)
void lstm_kernel(const float* __restrict__ w_ih1, const float* __restrict__ w_hh1,
                 const float* __restrict__ b_ih1, const float* __restrict__ b_hh1,
                 const float* __restrict__ w_ih2, const float* __restrict__ w_hh2,
                 const float* __restrict__ b_ih2, const float* __restrict__ b_hh2,
                 const float* __restrict__ w_fc1, const float* __restrict__ b_fc1,
                 const float* __restrict__ w_fc2, const float* __restrict__ b_fc2,
                 float* __restrict__ out) {
    __shared__ __align__(16) float sb[2][MB][SSTR];
    __shared__ float fcs[MB][16];

    const int tid  = threadIdx.x;
    const int lane = tid & 31;
    const int wrp  = tid >> 5;
    const int b0   = blockIdx.x * MB;

    // ---- layer-1 role: (kh, gate, j) ; warp holds 4 hidden units x 4 gates x 2 khalves
    const int kh  = lane & 1;
    const int g1  = (lane >> 1) & 3;
    const int j1  = wrp * 4 + ((lane >> 3) & 3);
    const int row1 = g1 * H1 + j1;
    // ---- layer-2 role: (kq, gate, j) ; warp holds 2 hidden units x 4 gates x 4 kquarters
    const int kq  = lane & 3;
    const int g2  = (lane >> 2) & 3;
    const int j2  = wrp * 2 + ((lane >> 4) & 1);
    const int row2 = g2 * H2 + j2;

    // ---- weights into registers (K-split slices, packed f32x2) ----
    ull wL1[24];
#pragma unroll
    for (int m = 0; m < 24; m++) {
        int k = kh * 48 + 2 * m;
        float f0 = (k < INP) ? w_ih1[row1 * INP + k]
                 : ((k < 32) ? 0.0f : w_hh1[row1 * H1 + (k - 32)]);
        int k1 = k + 1;
        float f1 = (k1 < INP) ? w_ih1[row1 * INP + k1]
                 : ((k1 < 32) ? 0.0f : w_hh1[row1 * H1 + (k1 - 32)]);
        wL1[m] = pack2(f0, f1);
    }
    const float bias1 = b_ih1[row1] + b_hh1[row1];

    ull wL2[12];
#pragma unroll
    for (int m = 0; m < 12; m++) {
        int k = kq * 24 + 2 * m;
        float f0 = (k < H1) ? w_ih2[row2 * H1 + k] : w_hh2[row2 * H2 + (k - H1)];
        int k1 = k + 1;
        float f1 = (k1 < H1) ? w_ih2[row2 * H1 + k1] : w_hh2[row2 * H2 + (k1 - H1)];
        wL2[m] = pack2(f0, f1);
    }
    const float bias2 = b_ih2[row2] + b_hh2[row2];

    // unified activation constants: act = a * sigm(|s|*v) + b ; tanh = 2*sigm(2v)-1
    const float m1 = (g1 == 2) ? -2.885390081777927f : -1.4426950408889634f;
    const float a1 = (g1 == 2) ? 2.0f : 1.0f;
    const float bb1 = (g1 == 2) ? -1.0f : 0.0f;
    const float m2 = (g2 == 2) ? -2.885390081777927f : -1.4426950408889634f;
    const float a2 = (g2 == 2) ? 2.0f : 1.0f;
    const float bb2 = (g2 == 2) ? -1.0f : 0.0f;

    float c1[2] = {0.0f, 0.0f};   // cell state, r = 2*kh + rr
    float c2 = 0.0f;              // cell state, r = kq

    // ---- zero both buffers, then overlay x[0] ----
    for (int i = tid; i < 2 * MB * SSTR; i += NTHR) ((float*)sb)[i] = 0.0f;
    __syncthreads();
    float rx = 0.0f;
    if (tid < MB * INP) {
        int r = tid / INP, i = tid % INP;
        sb[0][r][i] = g_xT[b0 * INP + tid];
        rx = g_xT[1 * (BATCH * INP) + b0 * INP + tid];   // x[1] staged in reg
    }
    __syncthreads();

    for (int t = 0; t < T_STEPS; t++) {
        float* __restrict__ sin  = &sb[t & 1][0][0];
        float* __restrict__ sout = &sb[(t & 1) ^ 1][0][0];

        // stage x[t+1] into OUT.x ; prefetch x[t+2]
        if (tid < MB * INP) {
            sout[(tid / INP) * SSTR + (tid % INP)] = rx;
            if (t + 2 < T_STEPS)
                rx = g_xT[(t + 2) * (BATCH * INP) + b0 * INP + tid];
        }
        // copy IN.h2new (=h2[t-1]) -> OUT.h2copy so L2's K-vector is contiguous
        if (tid < 32) {
            int r = tid >> 3, sg = (tid & 7) * 4;
            ulonglong2 v = *(const ulonglong2*)&sin[r * SSTR + 128 + sg];
            *(ulonglong2*)&sout[r * SSTR + 96 + sg] = v;
        }

        // ===== layer-1 gates: acc over this lane's 48-float K-slice, all 4 r =====
        ull acc0 = pack2(0.f, 0.f), acc1 = acc0, acc2r = acc0, acc3 = acc0;
        const float* base = &sin[kh * 48];
#pragma unroll
        for (int mm = 0; mm < 12; mm++) {
            ulonglong2 p0 = *(const ulonglong2*)(base + 0 * SSTR + mm * 4);
            ulonglong2 p1 = *(const ulonglong2*)(base + 1 * SSTR + mm * 4);
            ulonglong2 p2 = *(const ulonglong2*)(base + 2 * SSTR + mm * 4);
            ulonglong2 p3 = *(const ulonglong2*)(base + 3 * SSTR + mm * 4);
            ffma2(acc0, wL1[2 * mm], p0.x); ffma2(acc0, wL1[2 * mm + 1], p0.y);
            ffma2(acc1, wL1[2 * mm], p1.x); ffma2(acc1, wL1[2 * mm + 1], p1.y);
            ffma2(acc2r, wL1[2 * mm], p2.x); ffma2(acc2r, wL1[2 * mm + 1], p2.y);
            ffma2(acc3, wL1[2 * mm], p3.x); ffma2(acc3, wL1[2 * mm + 1], p3.y);
        }
        float t0 = hsum2(acc0), t1 = hsum2(acc1), t2 = hsum2(acc2r), t3 = hsum2(acc3);
        t0 += __shfl_xor_sync(0xffffffffu, t0, 1);
        t1 += __shfl_xor_sync(0xffffffffu, t1, 1);
        t2 += __shfl_xor_sync(0xffffffffu, t2, 1);
        t3 += __shfl_xor_sync(0xffffffffu, t3, 1);
        // this lane activates r = 2*kh + {0,1}
        float v0 = (kh ? t2 : t0) + bias1;
        float v1 = (kh ? t3 : t1) + bias1;
        float act0 = fmaf(a1, rcpf(1.0f + ex2f(m1 * v0)), bb1);
        float act1 = fmaf(a1, rcpf(1.0f + ex2f(m1 * v1)), bb1);

        {   // cell update via intra-warp gather (src keeps kh & j bits, swaps gate bits)
            const int gbase = lane & ~6;
#pragma unroll
            for (int rr = 0; rr < 2; rr++) {
                float av = rr ? act1 : act0;
                float iv = __shfl_sync(0xffffffffu, av, gbase);
                float fv = __shfl_sync(0xffffffffu, av, gbase | 2);
                float gv = __shfl_sync(0xffffffffu, av, gbase | 4);
                float ov = __shfl_sync(0xffffffffu, av, gbase | 6);
                float c  = fmaf(fv, c1[rr], iv * gv);
                c1[rr] = c;
                float hv = ov * tanhc(c);
                if ((lane & 6) == 0)
                    sout[(2 * kh + rr) * SSTR + 32 + j1] = hv;
            }
        }
        __syncthreads();   // B-mid: h1[t], x[t+1], h2copy all visible

        // ===== layer-2 gates: K-vector = [h1(64) | h2copy(32)] contiguous in OUT =====
        ull q0 = pack2(0.f, 0.f), q1 = q0, q2 = q0, q3 = q0;
        const float* base2 = &sout[32 + kq * 24];
#pragma unroll
        for (int mm = 0; mm < 6; mm++) {
            ulonglong2 p0 = *(const ulonglong2*)(base2 + 0 * SSTR + mm * 4);
            ulonglong2 p1 = *(const ulonglong2*)(base2 + 1 * SSTR + mm * 4);
            ulonglong2 p2 = *(const ulonglong2*)(base2 + 2 * SSTR + mm * 4);
            ulonglong2 p3 = *(const ulonglong2*)(base2 + 3 * SSTR + mm * 4);
            ffma2(q0, wL2[2 * mm], p0.x); ffma2(q0, wL2[2 * mm + 1], p0.y);
            ffma2(q1, wL2[2 * mm], p1.x); ffma2(q1, wL2[2 * mm + 1], p1.y);
            ffma2(q2, wL2[2 * mm], p2.x); ffma2(q2, wL2[2 * mm + 1], p2.y);
            ffma2(q3, wL2[2 * mm], p3.x); ffma2(q3, wL2[2 * mm + 1], p3.y);
        }
        float tot2 = 0.0f;
        {
            float u0 = hsum2(q0), u1 = hsum2(q1), u2 = hsum2(q2), u3 = hsum2(q3);
            u0 += __shfl_xor_sync(0xffffffffu, u0, 1); u0 += __shfl_xor_sync(0xffffffffu, u0, 2);
            u1 += __shfl_xor_sync(0xffffffffu, u1, 1); u1 += __shfl_xor_sync(0xffffffffu, u1, 2);
            u2 += __shfl_xor_sync(0xffffffffu, u2, 1); u2 += __shfl_xor_sync(0xffffffffu, u2, 2);
            u3 += __shfl_xor_sync(0xffffffffu, u3, 1); u3 += __shfl_xor_sync(0xffffffffu, u3, 2);
            tot2 = (kq == 0) ? u0 : tot2;
            tot2 = (kq == 1) ? u1 : tot2;
            tot2 = (kq == 2) ? u2 : tot2;
            tot2 = (kq == 3) ? u3 : tot2;
        }
        tot2 += bias2;
        float act2 = fmaf(a2, rcpf(1.0f + ex2f(m2 * tot2)), bb2);
        {
            const int gbase2 = lane & ~12;
            float iv = __shfl_sync(0xffffffffu, act2, gbase2);
            float fv = __shfl_sync(0xffffffffu, act2, gbase2 | 4);
            float gv = __shfl_sync(0xffffffffu, act2, gbase2 | 8);
            float ov = __shfl_sync(0xffffffffu, act2, gbase2 | 12);
            float c  = fmaf(fv, c2, iv * gv);
            c2 = c;
            float hv = ov * tanhc(c);
            if ((lane & 12) == 0)
                sout[kq * SSTR + 128 + j2] = hv;
        }
        __syncthreads();   // B-end: h2[t] visible for next step's copy/L2
    }

    // ===== FC head on final h2 (in sb[0], h2new region) =====
    if (tid < MB * 16) {
        int r = tid >> 4, jj = tid & 15;
        float a = b_fc1[jj];
#pragma unroll
        for (int k = 0; k < H2; k++) a += w_fc1[jj * H2 + k] * sb[0][r][128 + k];
        fcs[r][jj] = fmaxf(a, 0.0f);
    }
    __syncthreads();
    if (tid < MB * 10) {
        int r = tid / 10, o = tid % 10;
        float a = b_fc2[o];
#pragma unroll
        for (int k = 0; k < 16; k++) a += w_fc2[o * 16 + k] * fcs[r][k];
        out[(b0 + r) * 10 + o] = a;
    }
}

extern "C" void kernel_launch(void* const* d_in, const int* in_sizes, int n_in,
                              void* d_out, int out_size) {
    const float* x     = (const float*)d_in[0];
    const float* w_ih1 = (const float*)d_in[1];
    const float* w_hh1 = (const float*)d_in[2];
    const float* b_ih1 = (const float*)d_in[3];
    const float* b_hh1 = (const float*)d_in[4];
    const float* w_ih2 = (const float*)d_in[5];
    const float* w_hh2 = (const float*)d_in[6];
    const float* b_ih2 = (const float*)d_in[7];
    const float* b_hh2 = (const float*)d_in[8];
    const float* w_fc1 = (const float*)d_in[9];
    const float* b_fc1 = (const float*)d_in[10];
    const float* w_fc2 = (const float*)d_in[11];
    const float* b_fc2 = (const float*)d_in[12];
    float* out = (float*)d_out;

    dim3 tb(32, 8);
    dim3 tg((T_STEPS + 31) / 32, (BATCH * INP) / 32);
    xpose_kernel<<<tg, tb>>>(x);

    lstm_kernel<<<NBLK, NTHR>>>(w_ih1, w_hh1, b_ih1, b_hh1,
                                w_ih2, w_hh2, b_ih2, b_hh2,
                                w_fc1, b_fc1, w_fc2, b_fc2, out);
}

// round 3
// speedup vs baseline: 1.1656x; 1.1222x over previous
#include <cuda_runtime.h>

#define T_STEPS 1000
#define BATCH   512
#define INP     26
#define H1      64
#define H2      32
#define MB      4
#define NBLK    (BATCH / MB)
#define SSTR    128          // floats per batch-row in step buffer
#define NTHR    768

typedef unsigned long long ull;

// Scratch: x transposed to [t][b][i] for coalesced per-step reads.
__device__ float g_xT[T_STEPS * BATCH * INP];

// ---------- f32x2 helpers ----------
__device__ __forceinline__ ull pack2(float lo, float hi) {
    ull r; asm("mov.b64 %0, {%1, %2};" : "=l"(r) : "f"(lo), "f"(hi)); return r;
}
__device__ __forceinline__ void ffma2(ull& d, ull a, ull b) {
    asm("fma.rn.f32x2 %0, %1, %2, %0;" : "+l"(d) : "l"(a), "l"(b));
}
__device__ __forceinline__ float hsum2(ull v) {
    float lo, hi; asm("mov.b64 {%0, %1}, %2;" : "=f"(lo), "=f"(hi) : "l"(v)); return lo + hi;
}
__device__ __forceinline__ float ex2f(float x) { float y; asm("ex2.approx.f32 %0, %1;" : "=f"(y) : "f"(x)); return y; }
__device__ __forceinline__ float rcpf(float x) { float y; asm("rcp.approx.f32 %0, %1;" : "=f"(y) : "f"(x)); return y; }
// tanh(c) = 2*sigmoid(2c)-1
__device__ __forceinline__ float tanhc(float c) {
    return fmaf(2.0f, rcpf(1.0f + ex2f(-2.885390081777927f * c)), -1.0f);
}

// ---------- transpose x: [B,26,T] -> [T, B*26] ----------
__global__ void xpose_kernel(const float* __restrict__ x) {
    __shared__ float tile[32][33];
    int t0 = blockIdx.x * 32;
    int r0 = blockIdx.y * 32;
    int tx = threadIdx.x, ty = threadIdx.y;
#pragma unroll
    for (int k = 0; k < 4; k++) {
        int t = t0 + tx;
        int r = r0 + ty + k * 8;
        if (t < T_STEPS) tile[ty + k * 8][tx] = x[r * T_STEPS + t];
    }
    __syncthreads();
#pragma unroll
    for (int k = 0; k < 4; k++) {
        int t = t0 + ty + k * 8;
        int r = r0 + tx;
        if (t < T_STEPS) g_xT[t * (BATCH * INP) + r] = tile[tx][ty + k * 8];
    }
}

// Buffer row layout (floats): [0..27] x (26 real + 2 pad, rest of K pad at 26..31 = 0)
//                             [32..95] h1   [96..127] h2
// Warps 0..15: layer-1 for step t.  Warps 16..23: layer-2 for step t-1 (skewed).
__global__ __launch_bounds__(NTHR, 1)
void lstm_kernel(const float* __restrict__ w_ih1, const float* __restrict__ w_hh1,
                 const float* __restrict__ b_ih1, const float* __restrict__ b_hh1,
                 const float* __restrict__ w_ih2, const float* __restrict__ w_hh2,
                 const float* __restrict__ b_ih2, const float* __restrict__ b_hh2,
                 const float* __restrict__ w_fc1, const float* __restrict__ b_fc1,
                 const float* __restrict__ w_fc2, const float* __restrict__ b_fc2,
                 float* __restrict__ out) {
    __shared__ __align__(16) float sb[2][MB][SSTR];
    __shared__ float fcs[MB][16];

    const int tid  = threadIdx.x;
    const int lane = tid & 31;
    const int wrp  = tid >> 5;
    const int b0   = blockIdx.x * MB;

    const bool isL1 = (tid < 512);
    const int  kh   = lane & 1;            // K-half
    const int  gg   = (lane >> 1) & 3;     // gate (i,f,g,o)
    const int  jsub = lane >> 3;           // unit-within-warp
    const int  jj   = (isL1 ? wrp * 4 : (wrp - 16) * 4) + jsub;
    const int  row  = isL1 ? (gg * H1 + jj) : (gg * H2 + jj);
    const int  koff = isL1 ? kh * 48 : 32 + kh * 48;

    // ---- weights: 24 packed f32x2 per thread (48-float K-half of one gate row)
    ull wt[24];
    float bias;
    if (isL1) {
#pragma unroll
        for (int m = 0; m < 24; m++) {
            int k = kh * 48 + 2 * m;
            float f0 = (k < INP) ? w_ih1[row * INP + k]
                     : ((k < 32) ? 0.0f : w_hh1[row * H1 + (k - 32)]);
            int k1 = k + 1;
            float f1 = (k1 < INP) ? w_ih1[row * INP + k1]
                     : ((k1 < 32) ? 0.0f : w_hh1[row * H1 + (k1 - 32)]);
            wt[m] = pack2(f0, f1);
        }
        bias = b_ih1[row] + b_hh1[row];
    } else {
#pragma unroll
        for (int m = 0; m < 24; m++) {
            int k = kh * 48 + 2 * m;
            float f0 = (k < H1) ? w_ih2[row * H1 + k] : w_hh2[row * H2 + (k - H1)];
            int k1 = k + 1;
            float f1 = (k1 < H1) ? w_ih2[row * H1 + k1] : w_hh2[row * H2 + (k1 - H1)];
            wt[m] = pack2(f0, f1);
        }
        bias = b_ih2[row] + b_hh2[row];
    }
    // unified activation: act = a*sigm(|s|*v)+b ; tanh = 2*sigm(2v)-1 (gate 2)
    const float mact = (gg == 2) ? -2.885390081777927f : -1.4426950408889634f;
    const float aact = (gg == 2) ? 2.0f : 1.0f;
    const float bact = (gg == 2) ? -1.0f : 0.0f;

    float cst[2] = {0.0f, 0.0f};   // L1 owners: c for r=2kh+{0,1}; L2 owner: cst[0]

    // ---- zero both buffers, overlay x[0], prefetch x[1] ----
    for (int i = tid; i < 2 * MB * SSTR; i += NTHR) ((float*)sb)[i] = 0.0f;
    __syncthreads();
    float rx = 0.0f;
    const int r_p = tid / INP, i_p = tid - r_p * INP;
    if (tid < MB * INP) {
        sb[0][r_p][i_p] = g_xT[b0 * INP + tid];
        rx = g_xT[BATCH * INP + b0 * INP + tid];
    }
    __syncthreads();

    for (int t = 0; t <= T_STEPS; t++) {
        float* __restrict__ sin  = &sb[t & 1][0][0];
        float* __restrict__ sout = &sb[(t & 1) ^ 1][0][0];

        // stage x[t+1] into OUT.x ; prefetch x[t+2] (L1-group threads)
        if (isL1 && tid < MB * INP) {
            if (t < T_STEPS - 1) sout[r_p * SSTR + i_p] = rx;
            if (t + 2 < T_STEPS) rx = g_xT[(t + 2) * (BATCH * INP) + b0 * INP + tid];
        }

        const bool active = isL1 ? (t < T_STEPS) : (t >= 1);
        if (active) {
            // ===== gates: 12x2 FFMA2 over this lane's 48-float K-slice, 4 batch rows
            float u[4];
#pragma unroll
            for (int rp = 0; rp < 2; rp++) {
                ull a0 = pack2(0.f, 0.f), a1 = pack2(0.f, 0.f);
                const float* bA = sin + (2 * rp) * SSTR + koff;
                const float* bB = bA + SSTR;
#pragma unroll
                for (int mm = 0; mm < 12; mm++) {
                    ulonglong2 pA = *(const ulonglong2*)(bA + mm * 4);
                    ulonglong2 pB = *(const ulonglong2*)(bB + mm * 4);
                    ffma2(a0, wt[2 * mm], pA.x); ffma2(a0, wt[2 * mm + 1], pA.y);
                    ffma2(a1, wt[2 * mm], pB.x); ffma2(a1, wt[2 * mm + 1], pB.y);
                }
                u[2 * rp]     = hsum2(a0);
                u[2 * rp + 1] = hsum2(a1);
            }
#pragma unroll
            for (int i = 0; i < 4; i++) u[i] += __shfl_xor_sync(0xffffffffu, u[i], 1);
            // this lane activates rows r = 2*kh + {0,1}
            float vlo = (kh ? u[2] : u[0]) + bias;
            float vhi = (kh ? u[3] : u[1]) + bias;
            float alo = fmaf(aact, rcpf(1.0f + ex2f(mact * vlo)), bact);
            float ahi = fmaf(aact, rcpf(1.0f + ex2f(mact * vhi)), bact);

            const int gb = lane & ~6;   // clear gate bits -> gather i,f,g,o
            if (isL1) {
#pragma unroll
                for (int rr = 0; rr < 2; rr++) {
                    float av = rr ? ahi : alo;
                    float iv = __shfl_sync(0xffffffffu, av, gb);
                    float fv = __shfl_sync(0xffffffffu, av, gb | 2);
                    float gv = __shfl_sync(0xffffffffu, av, gb | 4);
                    float ov = __shfl_sync(0xffffffffu, av, gb | 6);
                    float c  = fmaf(fv, cst[rr], iv * gv);
                    cst[rr] = c;
                    if ((lane & 6) == 0)
                        sout[(2 * kh + rr) * SSTR + 32 + jj] = ov * tanhc(c);
                }
            } else {
                float iL = __shfl_sync(0xffffffffu, alo, gb);
                float fL = __shfl_sync(0xffffffffu, alo, gb | 2);
                float gL = __shfl_sync(0xffffffffu, alo, gb | 4);
                float oL = __shfl_sync(0xffffffffu, alo, gb | 6);
                float iH = __shfl_sync(0xffffffffu, ahi, gb);
                float fH = __shfl_sync(0xffffffffu, ahi, gb | 2);
                float gH = __shfl_sync(0xffffffffu, ahi, gb | 4);
                float oH = __shfl_sync(0xffffffffu, ahi, gb | 6);
                if ((lane & 2) == 0) {          // gates 0,2 own a cell each
                    int hi = (lane >> 2) & 1;
                    float iv = hi ? iH : iL, fv = hi ? fH : fL;
                    float gv = hi ? gH : gL, ov = hi ? oH : oL;
                    float c  = fmaf(fv, cst[0], iv * gv);
                    cst[0] = c;
                    sout[(2 * kh + hi) * SSTR + 96 + jj] = ov * tanhc(c);
                }
            }
        }
        __syncthreads();
    }

    // ===== FC head on final h2 (tick 1000 wrote sout = sb[1]) =====
    if (tid < MB * 16) {
        int r = tid >> 4, q = tid & 15;
        float a = b_fc1[q];
#pragma unroll
        for (int k = 0; k < H2; k++) a += w_fc1[q * H2 + k] * sb[1][r][96 + k];
        fcs[r][q] = fmaxf(a, 0.0f);
    }
    __syncthreads();
    if (tid < MB * 10) {
        int r = tid / 10, o = tid % 10;
        float a = b_fc2[o];
#pragma unroll
        for (int k = 0; k < 16; k++) a += w_fc2[o * 16 + k] * fcs[r][k];
        out[(b0 + r) * 10 + o] = a;
    }
}

extern "C" void kernel_launch(void* const* d_in, const int* in_sizes, int n_in,
                              void* d_out, int out_size) {
    const float* x     = (const float*)d_in[0];
    const float* w_ih1 = (const float*)d_in[1];
    const float* w_hh1 = (const float*)d_in[2];
    const float* b_ih1 = (const float*)d_in[3];
    const float* b_hh1 = (const float*)d_in[4];
    const float* w_ih2 = (const float*)d_in[5];
    const float* w_hh2 = (const float*)d_in[6];
    const float* b_ih2 = (const float*)d_in[7];
    const float* b_hh2 = (const float*)d_in[8];
    const float* w_fc1 = (const float*)d_in[9];
    const float* b_fc1 = (const float*)d_in[10];
    const float* w_fc2 = (const float*)d_in[11];
    const float* b_fc2 = (const float*)d_in[12];
    float* out = (float*)d_out;

    dim3 tb(32, 8);
    dim3 tg((T_STEPS + 31) / 32, (BATCH * INP) / 32);
    xpose_kernel<<<tg, tb>>>(x);

    lstm_kernel<<<NBLK, NTHR>>>(w_ih1, w_hh1, b_ih1, b_hh1,
                                w_ih2, w_hh2, b_ih2, b_hh2,
                                w_fc1, b_fc1, w_fc2, b_fc2, out);
}

// round 4
// speedup vs baseline: 1.1975x; 1.0274x over previous
#include <cuda_runtime.h>

#define T_STEPS 1000
#define BATCH   512
#define INP     26
#define H1      64
#define H2      32
#define MB      4
#define NBLK    (BATCH / MB)
#define SSTR    128          // floats per batch-row in step buffer
#define NTHR    768

typedef unsigned long long ull;

// Scratch: x transposed to [t][b][i] for coalesced per-step reads.
__device__ float g_xT[T_STEPS * BATCH * INP];

// ---------- f32x2 helpers ----------
__device__ __forceinline__ ull pack2(float lo, float hi) {
    ull r; asm("mov.b64 %0, {%1, %2};" : "=l"(r) : "f"(lo), "f"(hi)); return r;
}
__device__ __forceinline__ void ffma2(ull& d, ull a, ull b) {
    asm("fma.rn.f32x2 %0, %1, %2, %0;" : "+l"(d) : "l"(a), "l"(b));
}
__device__ __forceinline__ float hsum2(ull v) {
    float lo, hi; asm("mov.b64 {%0, %1}, %2;" : "=f"(lo), "=f"(hi) : "l"(v)); return lo + hi;
}
__device__ __forceinline__ float ex2f(float x) { float y; asm("ex2.approx.f32 %0, %1;" : "=f"(y) : "f"(x)); return y; }
__device__ __forceinline__ float rcpf(float x) { float y; asm("rcp.approx.f32 %0, %1;" : "=f"(y) : "f"(x)); return y; }
// tanh(c) = 2*sigmoid(2c)-1
__device__ __forceinline__ float tanhc(float c) {
    return fmaf(2.0f, rcpf(1.0f + ex2f(-2.885390081777927f * c)), -1.0f);
}

// ---------- transpose x: [B,26,T] -> [T, B*26] ----------
__global__ void xpose_kernel(const float* __restrict__ x) {
    __shared__ float tile[32][33];
    int t0 = blockIdx.x * 32;
    int r0 = blockIdx.y * 32;
    int tx = threadIdx.x, ty = threadIdx.y;
#pragma unroll
    for (int k = 0; k < 4; k++) {
        int t = t0 + tx;
        int r = r0 + ty + k * 8;
        if (t < T_STEPS) tile[ty + k * 8][tx] = x[r * T_STEPS + t];
    }
    __syncthreads();
#pragma unroll
    for (int k = 0; k < 4; k++) {
        int t = t0 + ty + k * 8;
        int r = r0 + tx;
        if (t < T_STEPS) g_xT[t * (BATCH * INP) + r] = tile[tx][ty + k * 8];
    }
}

// L1 row weight at global K index k (K layout: x[0..25], pad[26..31], h1[32..95])
__device__ __forceinline__ float wl1f(const float* wih, const float* whh, int row, int k) {
    return (k < INP) ? wih[row * INP + k] : ((k < 32) ? 0.0f : whh[row * H1 + (k - 32)]);
}
// L2 row weight at global K index k in [32,128) (K layout: h1[32..95], h2[96..127])
__device__ __forceinline__ float wl2f(const float* wih, const float* whh, int row, int k) {
    return (k < 96) ? wih[row * H1 + (k - 32)] : whh[row * H2 + (k - 96)];
}

// Buffer row layout (floats): [0..27] x (26 real + pad=0 through 31)
//                             [32..95] h1   [96..127] h2
// Warps 0..15: layer-1 step t.  Warps 16..23: layer-2 step t-1 (skewed).
// Lane map: kq = lane&3 (K-quarter), gate = (lane>>2)&3, us = lane>>4.
// Each thread owns 2 adjacent gate-rows (units ju, ju+1) of its gate.
__global__ __launch_bounds__(NTHR, 1)
void lstm_kernel(const float* __restrict__ w_ih1, const float* __restrict__ w_hh1,
                 const float* __restrict__ b_ih1, const float* __restrict__ b_hh1,
                 const float* __restrict__ w_ih2, const float* __restrict__ w_hh2,
                 const float* __restrict__ b_ih2, const float* __restrict__ b_hh2,
                 const float* __restrict__ w_fc1, const float* __restrict__ b_fc1,
                 const float* __restrict__ w_fc2, const float* __restrict__ b_fc2,
                 float* __restrict__ out) {
    __shared__ __align__(16) float sb[2][MB][SSTR];
    __shared__ float fcs[MB][16];

    const int tid  = threadIdx.x;
    const int lane = tid & 31;
    const int wrp  = tid >> 5;
    const int b0   = blockIdx.x * MB;

    const bool isL1 = (wrp < 16);
    const int  kq   = lane & 3;
    const int  gg   = (lane >> 2) & 3;
    const int  us   = lane >> 4;
    const int  ju   = (isL1 ? wrp : wrp - 16) * 4 + us * 2;
    const int  Hd   = isL1 ? H1 : H2;
    const int  row0 = gg * Hd + ju;
    const int  row1 = row0 + 1;
    const int  koff = (isL1 ? 0 : 32) + kq * 24;

    // ---- weights: two gate-rows, 24-float K-quarter each, packed f32x2 ----
    ull w0[12], w1[12];
    float bias0, bias1;
    if (isL1) {
#pragma unroll
        for (int m = 0; m < 12; m++) {
            int k = koff + 2 * m;
            w0[m] = pack2(wl1f(w_ih1, w_hh1, row0, k), wl1f(w_ih1, w_hh1, row0, k + 1));
            w1[m] = pack2(wl1f(w_ih1, w_hh1, row1, k), wl1f(w_ih1, w_hh1, row1, k + 1));
        }
        bias0 = b_ih1[row0] + b_hh1[row0];
        bias1 = b_ih1[row1] + b_hh1[row1];
    } else {
#pragma unroll
        for (int m = 0; m < 12; m++) {
            int k = koff + 2 * m;
            w0[m] = pack2(wl2f(w_ih2, w_hh2, row0, k), wl2f(w_ih2, w_hh2, row0, k + 1));
            w1[m] = pack2(wl2f(w_ih2, w_hh2, row1, k), wl2f(w_ih2, w_hh2, row1, k + 1));
        }
        bias0 = b_ih2[row0] + b_hh2[row0];
        bias1 = b_ih2[row1] + b_hh2[row1];
    }
    // unified activation: act = a*sigm(|s|*v)+b ; tanh = 2*sigm(2v)-1 (gate 2)
    const float mact = (gg == 2) ? -2.885390081777927f : -1.4426950408889634f;
    const float aact = (gg == 2) ? 2.0f : 1.0f;
    const float bact = (gg == 2) ? -1.0f : 0.0f;

    float cs0 = 0.0f, cs1 = 0.0f;   // cells owned by gate-0 lanes: units ju, ju+1, batch kq

    // ---- zero both buffers, overlay x[0], prefetch x[1] ----
    for (int i = tid; i < 2 * MB * SSTR; i += NTHR) ((float*)sb)[i] = 0.0f;
    __syncthreads();
    float rx = 0.0f;
    const int r_p = tid / INP, i_p = tid - r_p * INP;
    if (tid < MB * INP) {
        sb[0][r_p][i_p] = g_xT[b0 * INP + tid];
        rx = g_xT[BATCH * INP + b0 * INP + tid];
    }
    __syncthreads();

    for (int t = 0; t <= T_STEPS; t++) {
        const float* __restrict__ sin = &sb[t & 1][0][0];
        float* __restrict__ sout = &sb[(t & 1) ^ 1][0][0];

        // stage x[t+1] into OUT.x ; prefetch x[t+2]
        if (tid < MB * INP) {
            if (t < T_STEPS - 1) sout[r_p * SSTR + i_p] = rx;
            if (t + 2 < T_STEPS) rx = g_xT[(t + 2) * (BATCH * INP) + b0 * INP + tid];
        }

        const bool active = isL1 ? (t < T_STEPS) : (t >= 1);
        if (active) {
            // ===== 24 LDS.128 feed 96 FFMA2 (2 rows x 4 batch x 12) =====
            ull acc0[4], acc1[4];
#pragma unroll
            for (int r = 0; r < 4; r++) { acc0[r] = pack2(0.f, 0.f); acc1[r] = pack2(0.f, 0.f); }
#pragma unroll
            for (int r = 0; r < 4; r++) {
                const float* bp = sin + r * SSTR + koff;
#pragma unroll
                for (int mm = 0; mm < 6; mm++) {
                    ulonglong2 p = *(const ulonglong2*)(bp + mm * 4);
                    ffma2(acc0[r], w0[2 * mm], p.x); ffma2(acc0[r], w0[2 * mm + 1], p.y);
                    ffma2(acc1[r], w1[2 * mm], p.x); ffma2(acc1[r], w1[2 * mm + 1], p.y);
                }
            }
            float u0[4], u1[4];
#pragma unroll
            for (int r = 0; r < 4; r++) { u0[r] = hsum2(acc0[r]); u1[r] = hsum2(acc1[r]); }
            // butterfly over kq (lane bits 0-1)
#pragma unroll
            for (int r = 0; r < 4; r++) {
                u0[r] += __shfl_xor_sync(0xffffffffu, u0[r], 1);
                u1[r] += __shfl_xor_sync(0xffffffffu, u1[r], 1);
            }
#pragma unroll
            for (int r = 0; r < 4; r++) {
                u0[r] += __shfl_xor_sync(0xffffffffu, u0[r], 2);
                u1[r] += __shfl_xor_sync(0xffffffffu, u1[r], 2);
            }
            // this lane activates batch r = kq for its two rows
            float v0 = (kq & 2) ? ((kq & 1) ? u0[3] : u0[2]) : ((kq & 1) ? u0[1] : u0[0]);
            float v1 = (kq & 2) ? ((kq & 1) ? u1[3] : u1[2]) : ((kq & 1) ? u1[1] : u1[0]);
            v0 += bias0;
            v1 += bias1;
            float a0 = fmaf(aact, rcpf(1.0f + ex2f(mact * v0)), bact);
            float a1 = fmaf(aact, rcpf(1.0f + ex2f(mact * v1)), bact);

            // gather i,f,g,o across gate bits (lane bits 2-3)
            const int gb = lane & ~12;
            float i0 = __shfl_sync(0xffffffffu, a0, gb);
            float f0 = __shfl_sync(0xffffffffu, a0, gb | 4);
            float g0 = __shfl_sync(0xffffffffu, a0, gb | 8);
            float o0 = __shfl_sync(0xffffffffu, a0, gb | 12);
            float i1 = __shfl_sync(0xffffffffu, a1, gb);
            float f1 = __shfl_sync(0xffffffffu, a1, gb | 4);
            float g1 = __shfl_sync(0xffffffffu, a1, gb | 8);
            float o1 = __shfl_sync(0xffffffffu, a1, gb | 12);

            if (gg == 0) {   // owner lanes: 8/warp, each owns 2 cells for batch kq
                float c0 = fmaf(f0, cs0, i0 * g0); cs0 = c0;
                float c1 = fmaf(f1, cs1, i1 * g1); cs1 = c1;
                float h0 = o0 * tanhc(c0);
                float h1 = o1 * tanhc(c1);
                float* wp = sout + kq * SSTR + (isL1 ? 32 : 96) + ju;
                *(float2*)wp = make_float2(h0, h1);
            }
        }
        __syncthreads();
    }

    // ===== FC head on final h2 (tick 1000 wrote h2[999] into sb[1]) =====
    if (tid < MB * 16) {
        int r = tid >> 4, q = tid & 15;
        float a = b_fc1[q];
#pragma unroll
        for (int k = 0; k < H2; k++) a += w_fc1[q * H2 + k] * sb[1][r][96 + k];
        fcs[r][q] = fmaxf(a, 0.0f);
    }
    __syncthreads();
    if (tid < MB * 10) {
        int r = tid / 10, o = tid % 10;
        float a = b_fc2[o];
#pragma unroll
        for (int k = 0; k < 16; k++) a += w_fc2[o * 16 + k] * fcs[r][k];
        out[(b0 + r) * 10 + o] = a;
    }
}

extern "C" void kernel_launch(void* const* d_in, const int* in_sizes, int n_in,
                              void* d_out, int out_size) {
    const float* x     = (const float*)d_in[0];
    const float* w_ih1 = (const float*)d_in[1];
    const float* w_hh1 = (const float*)d_in[2];
    const float* b_ih1 = (const float*)d_in[3];
    const float* b_hh1 = (const float*)d_in[4];
    const float* w_ih2 = (const float*)d_in[5];
    const float* w_hh2 = (const float*)d_in[6];
    const float* b_ih2 = (const float*)d_in[7];
    const float* b_hh2 = (const float*)d_in[8];
    const float* w_fc1 = (const float*)d_in[9];
    const float* b_fc1 = (const float*)d_in[10];
    const float* w_fc2 = (const float*)d_in[11];
    const float* b_fc2 = (const float*)d_in[12];
    float* out = (float*)d_out;

    dim3 tb(32, 8);
    dim3 tg((T_STEPS + 31) / 32, (BATCH * INP) / 32);
    xpose_kernel<<<tg, tb>>>(x);

    lstm_kernel<<<NBLK, NTHR>>>(w_ih1, w_hh1, b_ih1, b_hh1,
                                w_ih2, w_hh2, b_ih2, b_hh2,
                                w_fc1, b_fc1, w_fc2, b_fc2, out);
}

// round 5
// speedup vs baseline: 1.2839x; 1.0721x over previous
#include <cuda_runtime.h>

#define T_STEPS 1000
#define BATCH   512
#define INP     26
#define H1      64
#define H2      32
#define MB      4
#define NBLK    (BATCH / MB)
#define SSTR    128          // floats per batch-row in step buffer
#define NTHR    384

typedef unsigned long long ull;

// Scratch: x transposed to [t][b][i] for coalesced per-step reads.
__device__ float g_xT[T_STEPS * BATCH * INP];

// ---------- f32x2 helpers ----------
__device__ __forceinline__ ull pack2(float lo, float hi) {
    ull r; asm("mov.b64 %0, {%1, %2};" : "=l"(r) : "f"(lo), "f"(hi)); return r;
}
__device__ __forceinline__ void ffma2(ull& d, ull a, ull b) {
    asm("fma.rn.f32x2 %0, %1, %2, %0;" : "+l"(d) : "l"(a), "l"(b));
}
__device__ __forceinline__ float hsum2(ull v) {
    float lo, hi; asm("mov.b64 {%0, %1}, %2;" : "=f"(lo), "=f"(hi) : "l"(v)); return lo + hi;
}
__device__ __forceinline__ float ex2f(float x) { float y; asm("ex2.approx.f32 %0, %1;" : "=f"(y) : "f"(x)); return y; }
__device__ __forceinline__ float rcpf(float x) { float y; asm("rcp.approx.f32 %0, %1;" : "=f"(y) : "f"(x)); return y; }
// tanh(c) = 2*sigmoid(2c)-1
__device__ __forceinline__ float tanhc(float c) {
    return fmaf(2.0f, rcpf(1.0f + ex2f(-2.885390081777927f * c)), -1.0f);
}

// ---------- transpose x: [B,26,T] -> [T, B*26] ----------
__global__ void xpose_kernel(const float* __restrict__ x) {
    __shared__ float tile[32][33];
    int t0 = blockIdx.x * 32;
    int r0 = blockIdx.y * 32;
    int tx = threadIdx.x, ty = threadIdx.y;
#pragma unroll
    for (int k = 0; k < 4; k++) {
        int t = t0 + tx;
        int r = r0 + ty + k * 8;
        if (t < T_STEPS) tile[ty + k * 8][tx] = x[r * T_STEPS + t];
    }
    __syncthreads();
#pragma unroll
    for (int k = 0; k < 4; k++) {
        int t = t0 + ty + k * 8;
        int r = r0 + tx;
        if (t < T_STEPS) g_xT[t * (BATCH * INP) + r] = tile[tx][ty + k * 8];
    }
}

// Buffer row layout (floats): [0..25] x, [26..31] pad=0, [32..95] h1, [96..127] h2.
// Warps 0..7: layer-1 step t (256 threads = 256 gate rows, full K in regs).
// Warps 8..11: layer-2 step t-1 (128 threads = 128 gate rows, full K in regs).
// Lane map: gate = lane&3, unit = warp*8 + (lane>>2). All 4 gates of a unit
// sit in adjacent lanes -> cell update via 3 shfl_down, no reduction needed.
__global__ __launch_bounds__(NTHR, 1)
void lstm_kernel(const float* __restrict__ w_ih1, const float* __restrict__ w_hh1,
                 const float* __restrict__ b_ih1, const float* __restrict__ b_hh1,
                 const float* __restrict__ w_ih2, const float* __restrict__ w_hh2,
                 const float* __restrict__ b_ih2, const float* __restrict__ b_hh2,
                 const float* __restrict__ w_fc1, const float* __restrict__ b_fc1,
                 const float* __restrict__ w_fc2, const float* __restrict__ b_fc2,
                 float* __restrict__ out) {
    __shared__ __align__(16) float sb[2][MB][SSTR];
    __shared__ float fcs[MB][16];

    const int tid  = threadIdx.x;
    const int lane = tid & 31;
    const int wrp  = tid >> 5;
    const int b0   = blockIdx.x * MB;

    const bool isL1 = (wrp < 8);
    const int  gt   = lane & 3;                         // gate i,f,g,o
    const int  un   = (isL1 ? wrp : wrp - 8) * 8 + (lane >> 2);  // unit
    const int  row  = isL1 ? (gt * H1 + un) : (gt * H2 + un);

    // ---- full-K weights in registers, packed f32x2 ----
    // L1: wt[0..12] = x part (26 floats), wt[13..44] = h1 part (64 floats)
    // L2: wt[0..31] = h1 part (64),       wt[32..47] = h2 part (32)
    ull wt[48];
    float bias;
    if (isL1) {
#pragma unroll
        for (int m = 0; m < 13; m++)
            wt[m] = pack2(w_ih1[row * INP + 2 * m], w_ih1[row * INP + 2 * m + 1]);
#pragma unroll
        for (int m = 0; m < 32; m++)
            wt[13 + m] = pack2(w_hh1[row * H1 + 2 * m], w_hh1[row * H1 + 2 * m + 1]);
#pragma unroll
        for (int m = 45; m < 48; m++) wt[m] = 0;
        bias = b_ih1[row] + b_hh1[row];
    } else {
#pragma unroll
        for (int m = 0; m < 32; m++)
            wt[m] = pack2(w_ih2[row * H1 + 2 * m], w_ih2[row * H1 + 2 * m + 1]);
#pragma unroll
        for (int m = 0; m < 16; m++)
            wt[32 + m] = pack2(w_hh2[row * H2 + 2 * m], w_hh2[row * H2 + 2 * m + 1]);
        bias = b_ih2[row] + b_hh2[row];
    }
    // unified activation: act = a*sigm(|s|*v)+b ; gate 2 (g) is tanh = 2*sigm(2v)-1
    const float mact = (gt == 2) ? -2.885390081777927f : -1.4426950408889634f;
    const float aact = (gt == 2) ? 2.0f : 1.0f;
    const float bact = (gt == 2) ? -1.0f : 0.0f;

    float cst[4] = {0.f, 0.f, 0.f, 0.f};   // cell state (owner lanes gt==0), per batch row

    // ---- zero both buffers, overlay x[0], prefetch x[1] ----
    for (int i = tid; i < 2 * MB * SSTR; i += NTHR) ((float*)sb)[i] = 0.0f;
    __syncthreads();
    float rx = 0.0f;
    const int r_p = tid / INP, i_p = tid - r_p * INP;
    if (tid < MB * INP) {
        sb[0][r_p][i_p] = g_xT[b0 * INP + tid];
        rx = g_xT[BATCH * INP + b0 * INP + tid];
    }
    __syncthreads();

    for (int t = 0; t <= T_STEPS; t++) {
        const float* __restrict__ sin = &sb[t & 1][0][0];
        float* __restrict__ sout = &sb[(t & 1) ^ 1][0][0];

        // stage x[t+1] into OUT.x ; prefetch x[t+2] (threads 0..103, all in L1 warps)
        if (tid < MB * INP) {
            if (t < T_STEPS - 1) sout[r_p * SSTR + i_p] = rx;
            if (t + 2 < T_STEPS) rx = g_xT[(t + 2) * (BATCH * INP) + b0 * INP + tid];
        }

        const bool active = isL1 ? (t < T_STEPS) : (t >= 1);
        if (active) {
            // ===== full-K dot product, 4 batch rows, operand loads are warp-broadcast
            ull acc[4];
#pragma unroll
            for (int r = 0; r < 4; r++) acc[r] = pack2(bias, 0.0f);

            if (isL1) {
#pragma unroll
                for (int r = 0; r < 4; r++) {
                    const float* bp = sin + r * SSTR;
#pragma unroll
                    for (int m = 0; m < 6; m++) {
                        ulonglong2 p = *(const ulonglong2*)(bp + m * 4);
                        ffma2(acc[r], wt[2 * m], p.x);
                        ffma2(acc[r], wt[2 * m + 1], p.y);
                    }
                    ull v = *(const ull*)(bp + 24);           // x[24..25]
                    ffma2(acc[r], wt[12], v);
#pragma unroll
                    for (int m = 0; m < 16; m++) {
                        ulonglong2 p = *(const ulonglong2*)(bp + 32 + m * 4);
                        ffma2(acc[r], wt[13 + 2 * m], p.x);
                        ffma2(acc[r], wt[14 + 2 * m], p.y);
                    }
                }
            } else {
#pragma unroll
                for (int r = 0; r < 4; r++) {
                    const float* bp = sin + r * SSTR + 32;    // [h1 | h2] contiguous
#pragma unroll
                    for (int m = 0; m < 24; m++) {
                        ulonglong2 p = *(const ulonglong2*)(bp + m * 4);
                        ffma2(acc[r], wt[2 * m], p.x);
                        ffma2(acc[r], wt[2 * m + 1], p.y);
                    }
                }
            }

            // ===== activation (no reduction: acc is the complete dot product)
            float av[4];
#pragma unroll
            for (int r = 0; r < 4; r++) {
                float v = hsum2(acc[r]);
                av[r] = fmaf(aact, rcpf(1.0f + ex2f(mact * v)), bact);
            }

            // ===== cell update: gates live in adjacent lanes (gt = lane&3)
            float hv[4];
#pragma unroll
            for (int r = 0; r < 4; r++) {
                float fv = __shfl_down_sync(0xffffffffu, av[r], 1);
                float gv = __shfl_down_sync(0xffffffffu, av[r], 2);
                float ov = __shfl_down_sync(0xffffffffu, av[r], 3);
                if (gt == 0) {
                    float c = fmaf(fv, cst[r], av[r] * gv);
                    cst[r] = c;
                    hv[r] = ov * tanhc(c);
                }
            }
            if (gt == 0) {
                const int ho = isL1 ? 32 : 96;
#pragma unroll
                for (int r = 0; r < 4; r++)
                    sout[r * SSTR + ho + un] = hv[r];
            }
        }
        __syncthreads();
    }

    // ===== FC head on final h2 (tick 1000 wrote h2[999] into sb[1]) =====
    if (tid < MB * 16) {
        int r = tid >> 4, q = tid & 15;
        float a = b_fc1[q];
#pragma unroll
        for (int k = 0; k < H2; k++) a += w_fc1[q * H2 + k] * sb[1][r][96 + k];
        fcs[r][q] = fmaxf(a, 0.0f);
    }
    __syncthreads();
    if (tid < MB * 10) {
        int r = tid / 10, o = tid % 10;
        float a = b_fc2[o];
#pragma unroll
        for (int k = 0; k < 16; k++) a += w_fc2[o * 16 + k] * fcs[r][k];
        out[(b0 + r) * 10 + o] = a;
    }
}

extern "C" void kernel_launch(void* const* d_in, const int* in_sizes, int n_in,
                              void* d_out, int out_size) {
    const float* x     = (const float*)d_in[0];
    const float* w_ih1 = (const float*)d_in[1];
    const float* w_hh1 = (const float*)d_in[2];
    const float* b_ih1 = (const float*)d_in[3];
    const float* b_hh1 = (const float*)d_in[4];
    const float* w_ih2 = (const float*)d_in[5];
    const float* w_hh2 = (const float*)d_in[6];
    const float* b_ih2 = (const float*)d_in[7];
    const float* b_hh2 = (const float*)d_in[8];
    const float* w_fc1 = (const float*)d_in[9];
    const float* b_fc1 = (const float*)d_in[10];
    const float* w_fc2 = (const float*)d_in[11];
    const float* b_fc2 = (const float*)d_in[12];
    float* out = (float*)d_out;

    dim3 tb(32, 8);
    dim3 tg((T_STEPS + 31) / 32, (BATCH * INP) / 32);
    xpose_kernel<<<tg, tb>>>(x);

    lstm_kernel<<<NBLK, NTHR>>>(w_ih1, w_hh1, b_ih1, b_hh1,
                                w_ih2, w_hh2, b_ih2, b_hh2,
                                w_fc1, b_fc1, w_fc2, b_fc2, out);
}

// round 6
// speedup vs baseline: 1.3241x; 1.0313x over previous
#include <cuda_runtime.h>

#define T_STEPS 1000
#define BATCH   512
#define INP     26
#define H1      64
#define H2      32
#define MB      4
#define NBLK    (BATCH / MB)
#define NTHR    384
#define XSTR    28

typedef unsigned long long ull;

// Scratch: x transposed to [t][b][i] for coalesced per-step reads.
__device__ float g_xT[T_STEPS * BATCH * INP];

// ---------- f32x2 helpers ----------
__device__ __forceinline__ ull pack2(float lo, float hi) {
    ull r; asm("mov.b64 %0, {%1, %2};" : "=l"(r) : "f"(lo), "f"(hi)); return r;
}
__device__ __forceinline__ void ffma2(ull& d, ull a, ull b) {
    asm("fma.rn.f32x2 %0, %1, %2, %0;" : "+l"(d) : "l"(a), "l"(b));
}
__device__ __forceinline__ float hsum2(ull v) {
    float lo, hi; asm("mov.b64 {%0, %1}, %2;" : "=f"(lo), "=f"(hi) : "l"(v)); return lo + hi;
}
__device__ __forceinline__ float ex2f(float x) { float y; asm("ex2.approx.f32 %0, %1;" : "=f"(y) : "f"(x)); return y; }
__device__ __forceinline__ float rcpf(float x) { float y; asm("rcp.approx.f32 %0, %1;" : "=f"(y) : "f"(x)); return y; }
// tanh(c) = 2*sigmoid(2c)-1
__device__ __forceinline__ float tanhc(float c) {
    return fmaf(2.0f, rcpf(1.0f + ex2f(-2.885390081777927f * c)), -1.0f);
}
// ---------- named barriers ----------
__device__ __forceinline__ void nbar_sync(int id, int cnt) {
    asm volatile("bar.sync %0, %1;" :: "r"(id), "r"(cnt) : "memory");
}
__device__ __forceinline__ void nbar_arrive(int id, int cnt) {
    asm volatile("bar.arrive %0, %1;" :: "r"(id), "r"(cnt) : "memory");
}

// ---------- transpose x: [B,26,T] -> [T, B*26] ----------
__global__ void xpose_kernel(const float* __restrict__ x) {
    __shared__ float tile[32][33];
    int t0 = blockIdx.x * 32;
    int r0 = blockIdx.y * 32;
    int tx = threadIdx.x, ty = threadIdx.y;
#pragma unroll
    for (int k = 0; k < 4; k++) {
        int t = t0 + tx;
        int r = r0 + ty + k * 8;
        if (t < T_STEPS) tile[ty + k * 8][tx] = x[r * T_STEPS + t];
    }
    __syncthreads();
#pragma unroll
    for (int k = 0; k < 4; k++) {
        int t = t0 + ty + k * 8;
        int r = r0 + tx;
        if (t < T_STEPS) g_xT[t * (BATCH * INP) + r] = tile[tx][ty + k * 8];
    }
}

// Warps 0..7: layer-1 (producer). Warps 8..11: layer-2 (consumer).
// h1 ring depth 2; full[s]=bar 2+s, empty[s]=bar 4+s (count 384).
// bar 1 = L1-internal (256), bar 6 = L2-internal (128).
// Lane map: gate = lane&3, unit = warpInGroup*8 + (lane>>2).
__global__ __launch_bounds__(NTHR, 1)
void lstm_kernel(const float* __restrict__ w_ih1, const float* __restrict__ w_hh1,
                 const float* __restrict__ b_ih1, const float* __restrict__ b_hh1,
                 const float* __restrict__ w_ih2, const float* __restrict__ w_hh2,
                 const float* __restrict__ b_ih2, const float* __restrict__ b_hh2,
                 const float* __restrict__ w_fc1, const float* __restrict__ b_fc1,
                 const float* __restrict__ w_fc2, const float* __restrict__ b_fc2,
                 float* __restrict__ out) {
    __shared__ __align__(16) float xb[2][MB][XSTR];
    __shared__ __align__(16) float h1r[2][MB][H1];
    __shared__ __align__(16) float h2b[2][MB][H2];
    __shared__ float fcs[MB][16];

    const int tid  = threadIdx.x;
    const int lane = tid & 31;
    const int wrp  = tid >> 5;
    const int b0   = blockIdx.x * MB;

    const bool isL1 = (wrp < 8);
    const int  gt   = lane & 3;
    const int  un   = (isL1 ? wrp : wrp - 8) * 8 + (lane >> 2);
    const int  row  = isL1 ? (gt * H1 + un) : (gt * H2 + un);

    // ---- full-K weights in registers, packed f32x2 ----
    ull wt[48];
    float bias;
    if (isL1) {
#pragma unroll
        for (int m = 0; m < 13; m++)
            wt[m] = pack2(w_ih1[row * INP + 2 * m], w_ih1[row * INP + 2 * m + 1]);
#pragma unroll
        for (int m = 0; m < 32; m++)
            wt[13 + m] = pack2(w_hh1[row * H1 + 2 * m], w_hh1[row * H1 + 2 * m + 1]);
#pragma unroll
        for (int m = 45; m < 48; m++) wt[m] = 0;
        bias = b_ih1[row] + b_hh1[row];
    } else {
#pragma unroll
        for (int m = 0; m < 32; m++)
            wt[m] = pack2(w_ih2[row * H1 + 2 * m], w_ih2[row * H1 + 2 * m + 1]);
#pragma unroll
        for (int m = 0; m < 16; m++)
            wt[32 + m] = pack2(w_hh2[row * H2 + 2 * m], w_hh2[row * H2 + 2 * m + 1]);
        bias = b_ih2[row] + b_hh2[row];
    }
    const float mact = (gt == 2) ? -2.885390081777927f : -1.4426950408889634f;
    const float aact = (gt == 2) ? 2.0f : 1.0f;
    const float bact = (gt == 2) ? -1.0f : 0.0f;

    float cst[4] = {0.f, 0.f, 0.f, 0.f};

    // ---- zero buffers, overlay x[0], prefetch x[1] ----
    for (int i = tid; i < 2 * MB * XSTR; i += NTHR) ((float*)xb)[i] = 0.0f;
    for (int i = tid; i < 2 * MB * H1; i += NTHR) ((float*)h1r)[i] = 0.0f;
    for (int i = tid; i < 2 * MB * H2; i += NTHR) ((float*)h2b)[i] = 0.0f;
    __syncthreads();
    float rx = 0.0f;
    const int r_p = tid / INP, i_p = tid - r_p * INP;
    if (tid < MB * INP) {
        xb[0][r_p][i_p] = g_xT[b0 * INP + tid];
        rx = g_xT[BATCH * INP + b0 * INP + tid];
    }
    __syncthreads();

    if (isL1) {
        // ================= layer-1 producer loop =================
        for (int t = 0; t < T_STEPS; t++) {
            const float* __restrict__ xp = &xb[t & 1][0][0];
            const float* __restrict__ hp = &h1r[(t - 1) & 1][0][0];

            // stage x[t+1], prefetch x[t+2] (threads 0..103, all in L1)
            if (tid < MB * INP) {
                if (t < T_STEPS - 1) xb[(t + 1) & 1][r_p][i_p] = rx;
                if (t + 2 < T_STEPS) rx = g_xT[(t + 2) * (BATCH * INP) + b0 * INP + tid];
            }

            ull acc[4];
#pragma unroll
            for (int r = 0; r < 4; r++) acc[r] = pack2(bias, 0.0f);
#pragma unroll
            for (int r = 0; r < 4; r++) {
                const float* bx = xp + r * XSTR;
                const float* bh = hp + r * H1;
#pragma unroll
                for (int m = 0; m < 6; m++) {
                    ulonglong2 p = *(const ulonglong2*)(bx + m * 4);
                    ffma2(acc[r], wt[2 * m], p.x);
                    ffma2(acc[r], wt[2 * m + 1], p.y);
                }
                ull v = *(const ull*)(bx + 24);
                ffma2(acc[r], wt[12], v);
#pragma unroll
                for (int m = 0; m < 16; m++) {
                    ulonglong2 p = *(const ulonglong2*)(bh + m * 4);
                    ffma2(acc[r], wt[13 + 2 * m], p.x);
                    ffma2(acc[r], wt[14 + 2 * m], p.y);
                }
            }
            float av[4];
#pragma unroll
            for (int r = 0; r < 4; r++) {
                float v = hsum2(acc[r]);
                av[r] = fmaf(aact, rcpf(1.0f + ex2f(mact * v)), bact);
            }
            float hv[4];
#pragma unroll
            for (int r = 0; r < 4; r++) {
                float fv = __shfl_down_sync(0xffffffffu, av[r], 1);
                float gv = __shfl_down_sync(0xffffffffu, av[r], 2);
                float ov = __shfl_down_sync(0xffffffffu, av[r], 3);
                if (gt == 0) {
                    float c = fmaf(fv, cst[r], av[r] * gv);
                    cst[r] = c;
                    hv[r] = ov * tanhc(c);
                }
            }
            // ring slot t&1 must be free (L2 finished reading h1[t-2])
            if (t >= 2) nbar_sync(4 + (t & 1), 384);
            if (gt == 0) {
#pragma unroll
                for (int r = 0; r < 4; r++)
                    h1r[t & 1][r][un] = hv[r];
            }
            nbar_arrive(2 + (t & 1), 384);   // publish h1[t]
            nbar_sync(1, 256);               // L1-internal step boundary
        }
    } else {
        // ================= layer-2 consumer loop =================
        for (int t = 0; t < T_STEPS; t++) {
            nbar_sync(2 + (t & 1), 384);     // wait for h1[t]
            const float* __restrict__ hp = &h1r[t & 1][0][0];
            const float* __restrict__ gp = &h2b[(t - 1) & 1][0][0];

            ull acc[4];
#pragma unroll
            for (int r = 0; r < 4; r++) acc[r] = pack2(bias, 0.0f);
#pragma unroll
            for (int r = 0; r < 4; r++) {
                const float* bh = hp + r * H1;
                const float* bg = gp + r * H2;
#pragma unroll
                for (int m = 0; m < 16; m++) {
                    ulonglong2 p = *(const ulonglong2*)(bh + m * 4);
                    ffma2(acc[r], wt[2 * m], p.x);
                    ffma2(acc[r], wt[2 * m + 1], p.y);
                }
#pragma unroll
                for (int m = 0; m < 8; m++) {
                    ulonglong2 p = *(const ulonglong2*)(bg + m * 4);
                    ffma2(acc[r], wt[32 + 2 * m], p.x);
                    ffma2(acc[r], wt[33 + 2 * m], p.y);
                }
            }
            nbar_arrive(4 + (t & 1), 384);   // done reading h1[t] -> slot reusable

            float av[4];
#pragma unroll
            for (int r = 0; r < 4; r++) {
                float v = hsum2(acc[r]);
                av[r] = fmaf(aact, rcpf(1.0f + ex2f(mact * v)), bact);
            }
            float hv[4];
#pragma unroll
            for (int r = 0; r < 4; r++) {
                float fv = __shfl_down_sync(0xffffffffu, av[r], 1);
                float gv = __shfl_down_sync(0xffffffffu, av[r], 2);
                float ov = __shfl_down_sync(0xffffffffu, av[r], 3);
                if (gt == 0) {
                    float c = fmaf(fv, cst[r], av[r] * gv);
                    cst[r] = c;
                    hv[r] = ov * tanhc(c);
                }
            }
            if (gt == 0) {
#pragma unroll
                for (int r = 0; r < 4; r++)
                    h2b[t & 1][r][un] = hv[r];
            }
            nbar_sync(6, 128);               // L2-internal step boundary
        }
    }
    __syncthreads();

    // ===== FC head on final h2 (t=999 -> slot 1) =====
    if (tid < MB * 16) {
        int r = tid >> 4, q = tid & 15;
        float a = b_fc1[q];
#pragma unroll
        for (int k = 0; k < H2; k++) a += w_fc1[q * H2 + k] * h2b[1][r][k];
        fcs[r][q] = fmaxf(a, 0.0f);
    }
    __syncthreads();
    if (tid < MB * 10) {
        int r = tid / 10, o = tid % 10;
        float a = b_fc2[o];
#pragma unroll
        for (int k = 0; k < 16; k++) a += w_fc2[o * 16 + k] * fcs[r][k];
        out[(b0 + r) * 10 + o] = a;
    }
}

extern "C" void kernel_launch(void* const* d_in, const int* in_sizes, int n_in,
                              void* d_out, int out_size) {
    const float* x     = (const float*)d_in[0];
    const float* w_ih1 = (const float*)d_in[1];
    const float* w_hh1 = (const float*)d_in[2];
    const float* b_ih1 = (const float*)d_in[3];
    const float* b_hh1 = (const float*)d_in[4];
    const float* w_ih2 = (const float*)d_in[5];
    const float* w_hh2 = (const float*)d_in[6];
    const float* b_ih2 = (const float*)d_in[7];
    const float* b_hh2 = (const float*)d_in[8];
    const float* w_fc1 = (const float*)d_in[9];
    const float* b_fc1 = (const float*)d_in[10];
    const float* w_fc2 = (const float*)d_in[11];
    const float* b_fc2 = (const float*)d_in[12];
    float* out = (float*)d_out;

    dim3 tb(32, 8);
    dim3 tg((T_STEPS + 31) / 32, (BATCH * INP) / 32);
    xpose_kernel<<<tg, tb>>>(x);

    lstm_kernel<<<NBLK, NTHR>>>(w_ih1, w_hh1, b_ih1, b_hh1,
                                w_ih2, w_hh2, b_ih2, b_hh2,
                                w_fc1, b_fc1, w_fc2, b_fc2, out);
}

// round 7
// speedup vs baseline: 1.5536x; 1.1734x over previous
#include <cuda_runtime.h>

#define T_STEPS 1000
#define BATCH   512
#define INP     26
#define H1      64
#define H2      32
#define MB      4
#define NBLK    (BATCH / MB)
#define NTHR    384
#define SSTR    128

typedef unsigned long long ull;

// Scratch: x transposed to [t][b][i] for coalesced per-step reads.
__device__ float g_xT[T_STEPS * BATCH * INP];

// ---------- f32x2 helpers ----------
__device__ __forceinline__ ull pack2(float lo, float hi) {
    ull r; asm("mov.b64 %0, {%1, %2};" : "=l"(r) : "f"(lo), "f"(hi)); return r;
}
__device__ __forceinline__ void ffma2(ull& d, ull a, ull b) {
    asm("fma.rn.f32x2 %0, %1, %2, %0;" : "+l"(d) : "l"(a), "l"(b));
}
__device__ __forceinline__ float hsum2(ull v) {
    float lo, hi; asm("mov.b64 {%0, %1}, %2;" : "=f"(lo), "=f"(hi) : "l"(v)); return lo + hi;
}
__device__ __forceinline__ float ex2f(float x) { float y; asm("ex2.approx.f32 %0, %1;" : "=f"(y) : "f"(x)); return y; }
__device__ __forceinline__ float rcpf(float x) { float y; asm("rcp.approx.f32 %0, %1;" : "=f"(y) : "f"(x)); return y; }
// tanh(c) = 2*sigmoid(2c)-1
__device__ __forceinline__ float tanhc(float c) {
    return fmaf(2.0f, rcpf(1.0f + ex2f(-2.885390081777927f * c)), -1.0f);
}
// ---------- named barriers ----------
__device__ __forceinline__ void nbar_sync(int id, int cnt) {
    asm volatile("bar.sync %0, %1;" :: "r"(id), "r"(cnt) : "memory");
}
__device__ __forceinline__ void nbar_arrive(int id, int cnt) {
    asm volatile("bar.arrive %0, %1;" :: "r"(id), "r"(cnt) : "memory");
}

// ---------- transpose x: [B,26,T] -> [T, B*26] ----------
__global__ void xpose_kernel(const float* __restrict__ x) {
    __shared__ float tile[32][33];
    int t0 = blockIdx.x * 32;
    int r0 = blockIdx.y * 32;
    int tx = threadIdx.x, ty = threadIdx.y;
#pragma unroll
    for (int k = 0; k < 4; k++) {
        int t = t0 + tx;
        int r = r0 + ty + k * 8;
        if (t < T_STEPS) tile[ty + k * 8][tx] = x[r * T_STEPS + t];
    }
    __syncthreads();
#pragma unroll
    for (int k = 0; k < 4; k++) {
        int t = t0 + ty + k * 8;
        int r = r0 + tx;
        if (t < T_STEPS) g_xT[t * (BATCH * INP) + r] = tile[tx][ty + k * 8];
    }
}

// L1 weight at padded-K index k (0..95): x[0..25], pad[26..31], h1[32..95]
__device__ __forceinline__ float wl1f(const float* wih, const float* whh, int row, int k) {
    return (k < INP) ? wih[row * INP + k] : ((k < 32) ? 0.0f : whh[row * H1 + (k - 32)]);
}
// L2 weight at K index k (0..95): h1[0..63], h2[64..95]
__device__ __forceinline__ float wl2f(const float* wih, const float* whh, int row, int k) {
    return (k < H1) ? wih[row * H1 + k] : whh[row * H2 + (k - H1)];
}

// Slot layout (per batch row, 128 floats): [0..31] x (pad 0), [32..95] h1, [96..127] h2.
// Two slots, ring. L1 step t: reads slot (t+1)&1 (x[t], h1[t-1]), writes h1[t] to slot t&1,
// stages x[t+1] into slot t&1. L2 step t: reads slot t&1 (h1[t], h2[t-1]),
// writes h2[t] into slot (t+1)&1. Named bars as R6.
// Lane map: kh = lane&1 (K-half), gate = (lane>>1)&3, us = lane>>3 (2 adjacent units).
__global__ __launch_bounds__(NTHR, 1)
void lstm_kernel(const float* __restrict__ w_ih1, const float* __restrict__ w_hh1,
                 const float* __restrict__ b_ih1, const float* __restrict__ b_hh1,
                 const float* __restrict__ w_ih2, const float* __restrict__ w_hh2,
                 const float* __restrict__ b_ih2, const float* __restrict__ b_hh2,
                 const float* __restrict__ w_fc1, const float* __restrict__ b_fc1,
                 const float* __restrict__ w_fc2, const float* __restrict__ b_fc2,
                 float* __restrict__ out) {
    __shared__ __align__(16) float sb[2][MB][SSTR];
    __shared__ float fcs[MB][16];

    const int tid  = threadIdx.x;
    const int lane = tid & 31;
    const int wrp  = tid >> 5;
    const int b0   = blockIdx.x * MB;

    const bool isL1 = (wrp < 8);
    const int  wg   = isL1 ? wrp : wrp - 8;
    const int  kh   = lane & 1;
    const int  gt   = (lane >> 1) & 3;
    const int  us   = lane >> 3;
    const int  u0   = wg * 8 + us * 2;
    const int  Hd   = isL1 ? H1 : H2;
    const int  row0 = gt * Hd + u0;
    const int  row1 = row0 + 1;
    const int  koff = (isL1 ? 0 : 32) + kh * 48;   // buffer offset of this lane's K-slice

    // ---- weights: 2 rows x 24 packed pairs (48-float K-half each) ----
    ull w0[24], w1[24];
    float bias0, bias1;
    if (isL1) {
#pragma unroll
        for (int m = 0; m < 24; m++) {
            int k = kh * 48 + 2 * m;
            w0[m] = pack2(wl1f(w_ih1, w_hh1, row0, k), wl1f(w_ih1, w_hh1, row0, k + 1));
            w1[m] = pack2(wl1f(w_ih1, w_hh1, row1, k), wl1f(w_ih1, w_hh1, row1, k + 1));
        }
        bias0 = b_ih1[row0] + b_hh1[row0];
        bias1 = b_ih1[row1] + b_hh1[row1];
    } else {
#pragma unroll
        for (int m = 0; m < 24; m++) {
            int k = kh * 48 + 2 * m;
            w0[m] = pack2(wl2f(w_ih2, w_hh2, row0, k), wl2f(w_ih2, w_hh2, row0, k + 1));
            w1[m] = pack2(wl2f(w_ih2, w_hh2, row1, k), wl2f(w_ih2, w_hh2, row1, k + 1));
        }
        bias0 = b_ih2[row0] + b_hh2[row0];
        bias1 = b_ih2[row1] + b_hh2[row1];
    }
    // unified activation: act = a*sigm(|s|*v)+b ; gate 2 is tanh = 2*sigm(2v)-1
    const float mact = (gt == 2) ? -2.885390081777927f : -1.4426950408889634f;
    const float aact = (gt == 2) ? 2.0f : 1.0f;
    const float bact = (gt == 2) ? -1.0f : 0.0f;

    float cst[4] = {0.f, 0.f, 0.f, 0.f};   // owner cells: [row0/row1][q], r = 2*kh+q

    // ---- zero slots, overlay x[0] into slot 1, prefetch x[1] ----
    for (int i = tid; i < 2 * MB * SSTR; i += NTHR) ((float*)sb)[i] = 0.0f;
    __syncthreads();
    float rx = 0.0f;
    const int r_p = tid / INP, i_p = tid - r_p * INP;
    if (tid < MB * INP) {
        sb[1][r_p][i_p] = g_xT[b0 * INP + tid];
        rx = g_xT[BATCH * INP + b0 * INP + tid];
    }
    __syncthreads();

    if (isL1) {
        // ================= layer-1 producer =================
        for (int t = 0; t < T_STEPS; t++) {
            const float* __restrict__ sr = &sb[(t + 1) & 1][0][0];
            float* __restrict__ sw = &sb[t & 1][0][0];

            // stage x[t+1] into write slot; prefetch x[t+2] (threads 0..103)
            if (tid < MB * INP) {
                if (t < T_STEPS - 1) sw[r_p * SSTR + i_p] = rx;
                if (t + 2 < T_STEPS) rx = g_xT[(t + 2) * (BATCH * INP) + b0 * INP + tid];
            }

            ull a0[4], a1[4];
#pragma unroll
            for (int r = 0; r < 4; r++) { a0[r] = 0; a1[r] = 0; }
#pragma unroll
            for (int r = 0; r < 4; r++) {
                const float* bp = sr + r * SSTR + koff;
#pragma unroll
                for (int m = 0; m < 12; m++) {
                    ulonglong2 p = *(const ulonglong2*)(bp + m * 4);
                    ffma2(a0[r], w0[2 * m], p.x); ffma2(a0[r], w0[2 * m + 1], p.y);
                    ffma2(a1[r], w1[2 * m], p.x); ffma2(a1[r], w1[2 * m + 1], p.y);
                }
            }
            float s0[4], s1[4];
#pragma unroll
            for (int r = 0; r < 4; r++) { s0[r] = hsum2(a0[r]); s1[r] = hsum2(a1[r]); }
#pragma unroll
            for (int r = 0; r < 4; r++) {
                s0[r] += __shfl_xor_sync(0xffffffffu, s0[r], 1);
                s1[r] += __shfl_xor_sync(0xffffffffu, s1[r], 1);
            }
            // this lane activates batch r = 2*kh + q
            float v00 = (kh ? s0[2] : s0[0]) + bias0;
            float v01 = (kh ? s0[3] : s0[1]) + bias0;
            float v10 = (kh ? s1[2] : s1[0]) + bias1;
            float v11 = (kh ? s1[3] : s1[1]) + bias1;
            float e00 = fmaf(aact, rcpf(1.0f + ex2f(mact * v00)), bact);
            float e01 = fmaf(aact, rcpf(1.0f + ex2f(mact * v01)), bact);
            float e10 = fmaf(aact, rcpf(1.0f + ex2f(mact * v10)), bact);
            float e11 = fmaf(aact, rcpf(1.0f + ex2f(mact * v11)), bact);

            const int gb = lane & ~6;
            float f00 = __shfl_sync(0xffffffffu, e00, gb | 2);
            float g00 = __shfl_sync(0xffffffffu, e00, gb | 4);
            float o00 = __shfl_sync(0xffffffffu, e00, gb | 6);
            float f01 = __shfl_sync(0xffffffffu, e01, gb | 2);
            float g01 = __shfl_sync(0xffffffffu, e01, gb | 4);
            float o01 = __shfl_sync(0xffffffffu, e01, gb | 6);
            float f10 = __shfl_sync(0xffffffffu, e10, gb | 2);
            float g10 = __shfl_sync(0xffffffffu, e10, gb | 4);
            float o10 = __shfl_sync(0xffffffffu, e10, gb | 6);
            float f11 = __shfl_sync(0xffffffffu, e11, gb | 2);
            float g11 = __shfl_sync(0xffffffffu, e11, gb | 4);
            float o11 = __shfl_sync(0xffffffffu, e11, gb | 6);

            float2 hq0, hq1;
            if (gt == 0) {
                float c;
                c = fmaf(f00, cst[0], e00 * g00); cst[0] = c; hq0.x = o00 * tanhc(c);
                c = fmaf(f10, cst[1], e10 * g10); cst[1] = c; hq0.y = o10 * tanhc(c);
                c = fmaf(f01, cst[2], e01 * g01); cst[2] = c; hq1.x = o01 * tanhc(c);
                c = fmaf(f11, cst[3], e11 * g11); cst[3] = c; hq1.y = o11 * tanhc(c);
            }
            if (t >= 2) nbar_sync(4 + (t & 1), 384);   // slot free (L2 read h1[t-2])
            if (gt == 0) {
                *(float2*)&sw[(2 * kh + 0) * SSTR + 32 + u0] = hq0;
                *(float2*)&sw[(2 * kh + 1) * SSTR + 32 + u0] = hq1;
            }
            nbar_arrive(2 + (t & 1), 384);             // publish h1[t]
            nbar_sync(1, 256);                         // L1-internal boundary
        }
    } else {
        // ================= layer-2 consumer =================
        for (int t = 0; t < T_STEPS; t++) {
            nbar_sync(2 + (t & 1), 384);               // wait for h1[t]
            const float* __restrict__ sr = &sb[t & 1][0][0];
            float* __restrict__ sw = &sb[(t + 1) & 1][0][0];

            ull a0[4], a1[4];
#pragma unroll
            for (int r = 0; r < 4; r++) { a0[r] = 0; a1[r] = 0; }
#pragma unroll
            for (int r = 0; r < 4; r++) {
                const float* bp = sr + r * SSTR + koff;
#pragma unroll
                for (int m = 0; m < 12; m++) {
                    ulonglong2 p = *(const ulonglong2*)(bp + m * 4);
                    ffma2(a0[r], w0[2 * m], p.x); ffma2(a0[r], w0[2 * m + 1], p.y);
                    ffma2(a1[r], w1[2 * m], p.x); ffma2(a1[r], w1[2 * m + 1], p.y);
                }
            }
            nbar_arrive(4 + (t & 1), 384);             // done reading h1[t]

            float s0[4], s1[4];
#pragma unroll
            for (int r = 0; r < 4; r++) { s0[r] = hsum2(a0[r]); s1[r] = hsum2(a1[r]); }
#pragma unroll
            for (int r = 0; r < 4; r++) {
                s0[r] += __shfl_xor_sync(0xffffffffu, s0[r], 1);
                s1[r] += __shfl_xor_sync(0xffffffffu, s1[r], 1);
            }
            float v00 = (kh ? s0[2] : s0[0]) + bias0;
            float v01 = (kh ? s0[3] : s0[1]) + bias0;
            float v10 = (kh ? s1[2] : s1[0]) + bias1;
            float v11 = (kh ? s1[3] : s1[1]) + bias1;
            float e00 = fmaf(aact, rcpf(1.0f + ex2f(mact * v00)), bact);
            float e01 = fmaf(aact, rcpf(1.0f + ex2f(mact * v01)), bact);
            float e10 = fmaf(aact, rcpf(1.0f + ex2f(mact * v10)), bact);
            float e11 = fmaf(aact, rcpf(1.0f + ex2f(mact * v11)), bact);

            const int gb = lane & ~6;
            float f00 = __shfl_sync(0xffffffffu, e00, gb | 2);
            float g00 = __shfl_sync(0xffffffffu, e00, gb | 4);
            float o00 = __shfl_sync(0xffffffffu, e00, gb | 6);
            float f01 = __shfl_sync(0xffffffffu, e01, gb | 2);
            float g01 = __shfl_sync(0xffffffffu, e01, gb | 4);
            float o01 = __shfl_sync(0xffffffffu, e01, gb | 6);
            float f10 = __shfl_sync(0xffffffffu, e10, gb | 2);
            float g10 = __shfl_sync(0xffffffffu, e10, gb | 4);
            float o10 = __shfl_sync(0xffffffffu, e10, gb | 6);
            float f11 = __shfl_sync(0xffffffffu, e11, gb | 2);
            float g11 = __shfl_sync(0xffffffffu, e11, gb | 4);
            float o11 = __shfl_sync(0xffffffffu, e11, gb | 6);

            if (gt == 0) {
                float c;
                float2 hq0, hq1;
                c = fmaf(f00, cst[0], e00 * g00); cst[0] = c; hq0.x = o00 * tanhc(c);
                c = fmaf(f10, cst[1], e10 * g10); cst[1] = c; hq0.y = o10 * tanhc(c);
                c = fmaf(f01, cst[2], e01 * g01); cst[2] = c; hq1.x = o01 * tanhc(c);
                c = fmaf(f11, cst[3], e11 * g11); cst[3] = c; hq1.y = o11 * tanhc(c);
                *(float2*)&sw[(2 * kh + 0) * SSTR + 96 + u0] = hq0;
                *(float2*)&sw[(2 * kh + 1) * SSTR + 96 + u0] = hq1;
            }
            nbar_sync(6, 128);                         // L2-internal boundary
        }
    }
    __syncthreads();

    // ===== FC head on final h2 (t=999 wrote into slot 0, h2 region) =====
    if (tid < MB * 16) {
        int r = tid >> 4, q = tid & 15;
        float a = b_fc1[q];
#pragma unroll
        for (int k = 0; k < H2; k++) a += w_fc1[q * H2 + k] * sb[0][r][96 + k];
        fcs[r][q] = fmaxf(a, 0.0f);
    }
    __syncthreads();
    if (tid < MB * 10) {
        int r = tid / 10, o = tid % 10;
        float a = b_fc2[o];
#pragma unroll
        for (int k = 0; k < 16; k++) a += w_fc2[o * 16 + k] * fcs[r][k];
        out[(b0 + r) * 10 + o] = a;
    }
}

extern "C" void kernel_launch(void* const* d_in, const int* in_sizes, int n_in,
                              void* d_out, int out_size) {
    const float* x     = (const float*)d_in[0];
    const float* w_ih1 = (const float*)d_in[1];
    const float* w_hh1 = (const float*)d_in[2];
    const float* b_ih1 = (const float*)d_in[3];
    const float* b_hh1 = (const float*)d_in[4];
    const float* w_ih2 = (const float*)d_in[5];
    const float* w_hh2 = (const float*)d_in[6];
    const float* b_ih2 = (const float*)d_in[7];
    const float* b_hh2 = (const float*)d_in[8];
    const float* w_fc1 = (const float*)d_in[9];
    const float* b_fc1 = (const float*)d_in[10];
    const float* w_fc2 = (const float*)d_in[11];
    const float* b_fc2 = (const float*)d_in[12];
    float* out = (float*)d_out;

    dim3 tb(32, 8);
    dim3 tg((T_STEPS + 31) / 32, (BATCH * INP) / 32);
    xpose_kernel<<<tg, tb>>>(x);

    lstm_kernel<<<NBLK, NTHR>>>(w_ih1, w_hh1, b_ih1, b_hh1,
                                w_ih2, w_hh2, b_ih2, b_hh2,
                                w_fc1, b_fc1, w_fc2, b_fc2, out);
}